// round 15
// baseline (speedup 1.0000x reference)
#include <cuda_runtime.h>
#include <math.h>

// Problem constants
#define B_   8
#define C_   256
#define SQ_  4096   // 64*64 query pixels
#define SK_  1024   // 32*32 kv pixels
#define NH_  8
#define D_   32
#define NP_  4
#define OC_  64     // offset conv out channels = NH*NP*2
#define KC_  2304   // C_*9 im2col depth

// Scratch (device globals — no allocation allowed)
__device__ float g_q  [B_ * SQ_ * C_];   // (b, s, c)  channel-last
__device__ float g_k  [B_ * SK_ * C_];   // (b, sk, c)
__device__ float g_v  [B_ * SK_ * C_];   // (b, sk, c)
__device__ float g_off[B_ * SQ_ * OC_];  // (b, s, oc) -> final sample coords (kv pixel space)
__device__ float g_att[B_ * SQ_ * C_];   // (b, s, c)

// ---------------------------------------------------------------------------
// tf32 helpers (3xTF32 compensated mma)
// ---------------------------------------------------------------------------
__device__ __forceinline__ unsigned f2tf(float f) {
    unsigned r;
    asm("cvt.rna.tf32.f32 %0, %1;" : "=r"(r) : "f"(f));
    return r;
}
#define MMA_TF32(d0, d1, d2, d3, a0, a1, a2, a3, b0, b1)            \
    asm("mma.sync.aligned.m16n8k8.row.col.f32.tf32.tf32.f32 "       \
        "{%0,%1,%2,%3}, {%4,%5,%6,%7}, {%8,%9}, {%0,%1,%2,%3};"     \
        : "+f"(d0), "+f"(d1), "+f"(d2), "+f"(d3)                    \
        : "r"(a0), "r"(a1), "r"(a2), "r"(a3), "r"(b0), "r"(b1))

// ---------------------------------------------------------------------------
// Q projection: g_q[b][s][o] = sum_c q_w[o][c] * X[b][c][s]
// 64x64 tile, 16x16 threads, 4x4 microtile, k-major weight smem tile:
// mainloop = 2x LDS.128 + 16 FFMA per k-step.  (measured-good, unchanged)
// ---------------------------------------------------------------------------
__global__ __launch_bounds__(256)
void gemm_q_kernel(const float* __restrict__ X, const float* __restrict__ W) {
    int b  = blockIdx.z;
    int o0 = blockIdx.y * 64;
    int s0 = blockIdx.x * 64;
    int tx = threadIdx.x;          // 0..15 -> s
    int ty = threadIdx.y;          // 0..15 -> o
    int tid = ty * 16 + tx;

    __shared__ float Xs[16][64];   // [k][s]
    __shared__ float Wt[16][68];   // [k][o]  (k-major, pad 68 keeps float4 align)

    float acc[4][4];
#pragma unroll
    for (int i = 0; i < 4; i++)
#pragma unroll
        for (int j = 0; j < 4; j++) acc[i][j] = 0.f;

    for (int kc = 0; kc < C_; kc += 16) {
        {   // load X tile: 16k x 64s, float4 per thread
            int kk = tid >> 4;
            int sc = (tid & 15) * 4;
            float4 xv = *reinterpret_cast<const float4*>(
                X + ((size_t)(b * C_ + kc + kk)) * SQ_ + s0 + sc);
            *reinterpret_cast<float4*>(&Xs[kk][sc]) = xv;
        }
        {   // load W tile (o-major in gmem) and transpose into k-major smem
            int row = tid >> 2;            // o: 0..63
            int col = (tid & 3) * 4;       // k: 0,4,8,12
            float4 wv = *reinterpret_cast<const float4*>(
                W + (size_t)(o0 + row) * C_ + kc + col);
            Wt[col + 0][row] = wv.x;
            Wt[col + 1][row] = wv.y;
            Wt[col + 2][row] = wv.z;
            Wt[col + 3][row] = wv.w;
        }
        __syncthreads();
#pragma unroll
        for (int kk = 0; kk < 16; kk++) {
            float4 xv = *reinterpret_cast<const float4*>(&Xs[kk][tx * 4]);
            float4 wv = *reinterpret_cast<const float4*>(&Wt[kk][ty * 4]);
            acc[0][0] += xv.x * wv.x; acc[0][1] += xv.x * wv.y; acc[0][2] += xv.x * wv.z; acc[0][3] += xv.x * wv.w;
            acc[1][0] += xv.y * wv.x; acc[1][1] += xv.y * wv.y; acc[1][2] += xv.y * wv.z; acc[1][3] += xv.y * wv.w;
            acc[2][0] += xv.z * wv.x; acc[2][1] += xv.z * wv.y; acc[2][2] += xv.z * wv.z; acc[2][3] += xv.z * wv.w;
            acc[3][0] += xv.w * wv.x; acc[3][1] += xv.w * wv.y; acc[3][2] += xv.w * wv.z; acc[3][3] += xv.w * wv.w;
        }
        __syncthreads();
    }
#pragma unroll
    for (int i = 0; i < 4; i++) {
        float4 o4 = make_float4(acc[i][0], acc[i][1], acc[i][2], acc[i][3]);
        *reinterpret_cast<float4*>(
            g_q + ((size_t)b * SQ_ + s0 + tx * 4 + i) * C_ + o0 + ty * 4) = o4;
    }
}

// ---------------------------------------------------------------------------
// Fused K+V projection: one X tile in smem, two k-major weight tiles.
// (measured-good, unchanged)
// ---------------------------------------------------------------------------
__global__ __launch_bounds__(256)
void gemm_kv_kernel(const float* __restrict__ X,
                    const float* __restrict__ Wk_g,
                    const float* __restrict__ Wv_g) {
    int b  = blockIdx.z;
    int o0 = blockIdx.y * 64;
    int s0 = blockIdx.x * 64;
    int tx = threadIdx.x;
    int ty = threadIdx.y;
    int tid = ty * 16 + tx;

    __shared__ float Xs[16][64];
    __shared__ float Wkt[16][68];
    __shared__ float Wvt[16][68];

    float acck[4][4], accv[4][4];
#pragma unroll
    for (int i = 0; i < 4; i++)
#pragma unroll
        for (int j = 0; j < 4; j++) { acck[i][j] = 0.f; accv[i][j] = 0.f; }

    for (int kc = 0; kc < C_; kc += 16) {
        {
            int kk = tid >> 4;
            int sc = (tid & 15) * 4;
            float4 xv = *reinterpret_cast<const float4*>(
                X + ((size_t)(b * C_ + kc + kk)) * SK_ + s0 + sc);
            *reinterpret_cast<float4*>(&Xs[kk][sc]) = xv;
        }
        {
            int row = tid >> 2;
            int col = (tid & 3) * 4;
            size_t woff = (size_t)(o0 + row) * C_ + kc + col;
            float4 wk = *reinterpret_cast<const float4*>(Wk_g + woff);
            float4 wv = *reinterpret_cast<const float4*>(Wv_g + woff);
            Wkt[col + 0][row] = wk.x; Wkt[col + 1][row] = wk.y;
            Wkt[col + 2][row] = wk.z; Wkt[col + 3][row] = wk.w;
            Wvt[col + 0][row] = wv.x; Wvt[col + 1][row] = wv.y;
            Wvt[col + 2][row] = wv.z; Wvt[col + 3][row] = wv.w;
        }
        __syncthreads();
#pragma unroll
        for (int kk = 0; kk < 16; kk++) {
            float4 xv = *reinterpret_cast<const float4*>(&Xs[kk][tx * 4]);
            float4 kv4 = *reinterpret_cast<const float4*>(&Wkt[kk][ty * 4]);
            acck[0][0] += xv.x * kv4.x; acck[0][1] += xv.x * kv4.y; acck[0][2] += xv.x * kv4.z; acck[0][3] += xv.x * kv4.w;
            acck[1][0] += xv.y * kv4.x; acck[1][1] += xv.y * kv4.y; acck[1][2] += xv.y * kv4.z; acck[1][3] += xv.y * kv4.w;
            acck[2][0] += xv.z * kv4.x; acck[2][1] += xv.z * kv4.y; acck[2][2] += xv.z * kv4.z; acck[2][3] += xv.z * kv4.w;
            acck[3][0] += xv.w * kv4.x; acck[3][1] += xv.w * kv4.y; acck[3][2] += xv.w * kv4.z; acck[3][3] += xv.w * kv4.w;
            float4 vv4 = *reinterpret_cast<const float4*>(&Wvt[kk][ty * 4]);
            accv[0][0] += xv.x * vv4.x; accv[0][1] += xv.x * vv4.y; accv[0][2] += xv.x * vv4.z; accv[0][3] += xv.x * vv4.w;
            accv[1][0] += xv.y * vv4.x; accv[1][1] += xv.y * vv4.y; accv[1][2] += xv.y * vv4.z; accv[1][3] += xv.y * vv4.w;
            accv[2][0] += xv.z * vv4.x; accv[2][1] += xv.z * vv4.y; accv[2][2] += xv.z * vv4.z; accv[2][3] += xv.z * vv4.w;
            accv[3][0] += xv.w * vv4.x; accv[3][1] += xv.w * vv4.y; accv[3][2] += xv.w * vv4.z; accv[3][3] += xv.w * vv4.w;
        }
        __syncthreads();
    }
#pragma unroll
    for (int i = 0; i < 4; i++) {
        size_t base = ((size_t)b * SK_ + s0 + tx * 4 + i) * C_ + o0 + ty * 4;
        *reinterpret_cast<float4*>(g_k + base) =
            make_float4(acck[i][0], acck[i][1], acck[i][2], acck[i][3]);
        *reinterpret_cast<float4*>(g_v + base) =
            make_float4(accv[i][0], accv[i][1], accv[i][2], accv[i][3]);
    }
}

// ---------------------------------------------------------------------------
// GEMM B (final projection): out[b][o][s] = sum_c W[o][c] * g_att[b][s][c]
// (measured-good, unchanged)
// ---------------------------------------------------------------------------
__global__ __launch_bounds__(256)
void gemm_out_kernel(const float* __restrict__ W, float* __restrict__ Y) {
    int b  = blockIdx.z;
    int o0 = blockIdx.y * 64;
    int s0 = blockIdx.x * 64;
    int tx = threadIdx.x;          // s
    int ty = threadIdx.y;          // o
    int tid = ty * 16 + tx;

    __shared__ float As[16][68];   // [k][s]
    __shared__ float Wt[16][68];   // [k][o]

    float acc[4][4];
#pragma unroll
    for (int i = 0; i < 4; i++)
#pragma unroll
        for (int j = 0; j < 4; j++) acc[i][j] = 0.f;

    for (int kc = 0; kc < C_; kc += 16) {
        int row = tid >> 2;
        int col = (tid & 3) * 4;
        {
            float4 av = *reinterpret_cast<const float4*>(
                g_att + ((size_t)b * SQ_ + s0 + row) * C_ + kc + col);
            As[col + 0][row] = av.x; As[col + 1][row] = av.y;
            As[col + 2][row] = av.z; As[col + 3][row] = av.w;
        }
        {
            float4 wv = *reinterpret_cast<const float4*>(
                W + (size_t)(o0 + row) * C_ + kc + col);
            Wt[col + 0][row] = wv.x; Wt[col + 1][row] = wv.y;
            Wt[col + 2][row] = wv.z; Wt[col + 3][row] = wv.w;
        }
        __syncthreads();
#pragma unroll
        for (int kk = 0; kk < 16; kk++) {
            float4 xv = *reinterpret_cast<const float4*>(&As[kk][tx * 4]);
            float4 wv = *reinterpret_cast<const float4*>(&Wt[kk][ty * 4]);
            acc[0][0] += xv.x * wv.x; acc[0][1] += xv.x * wv.y; acc[0][2] += xv.x * wv.z; acc[0][3] += xv.x * wv.w;
            acc[1][0] += xv.y * wv.x; acc[1][1] += xv.y * wv.y; acc[1][2] += xv.y * wv.z; acc[1][3] += xv.y * wv.w;
            acc[2][0] += xv.z * wv.x; acc[2][1] += xv.z * wv.y; acc[2][2] += xv.z * wv.z; acc[2][3] += xv.z * wv.w;
            acc[3][0] += xv.w * wv.x; acc[3][1] += xv.w * wv.y; acc[3][2] += xv.w * wv.z; acc[3][3] += xv.w * wv.w;
        }
        __syncthreads();
    }
#pragma unroll
    for (int j = 0; j < 4; j++) {
        float4 o4 = make_float4(acc[0][j], acc[1][j], acc[2][j], acc[3][j]);
        *reinterpret_cast<float4*>(
            Y + ((size_t)b * C_ + o0 + ty * 4 + j) * SQ_ + s0 + tx * 4) = o4;
    }
}

// ---------------------------------------------------------------------------
// 3x3 SAME conv as implicit GEMM on TENSOR CORES (mma.sync tf32, 3xTF32).
// off(64oc, 64x) = W(64, 2304) x im2col(2304, 64x), one image row per block.
// 8 warps: warp = wm*2 + wn; warp computes m16 (oc = wm*16..+15) x n32
// (x = wn*32..+31) as 4 n-subtiles of m16n8k8.
// Fused coordinate epilogue: f = ((base + tanh(v+bias)*0.25) + 1)*16 - 0.5.
// ---------------------------------------------------------------------------
__global__ __launch_bounds__(256)
void conv_off_mma_kernel(const float* __restrict__ X, const float* __restrict__ W,
                         const float* __restrict__ bias) {
    int b  = blockIdx.y;
    int y  = blockIdx.x;           // image row = s-tile of 64 pixels
    int tid  = threadIdx.x;
    int warp = tid >> 5;
    int lane = tid & 31;
    int wm = warp >> 1;            // 0..3 -> oc0 = wm*16
    int wn = warp & 1;             // 0..1 -> x0  = wn*32
    int lg = lane >> 2;            // 0..7  (group id)
    int lt = lane & 3;             // 0..3  (thread in group)

    __shared__ float Xs[16][72];   // [k][x]
    __shared__ float Wt[16][72];   // [k][oc]

    float d[4][4];                 // [n-subtile][c-reg]
#pragma unroll
    for (int j = 0; j < 4; j++)
#pragma unroll
        for (int i = 0; i < 4; i++) d[j][i] = 0.f;

    for (int kc = 0; kc < KC_; kc += 16) {
        {   // gather im2col tile: 16 K-rows x 64 x-positions
            int kk   = tid >> 4;            // 0..15
            int xc   = (tid & 15) * 4;      // 0,4,...,60
            int kidx = kc + kk;
            int c    = kidx / 9;
            int r9   = kidx - c * 9;
            int ky   = r9 / 3 - 1;          // -1,0,1
            int kx   = r9 - (r9 / 3) * 3 - 1;
            int gy   = y + ky;
            float v0 = 0.f, v1 = 0.f, v2 = 0.f, v3 = 0.f;
            if (gy >= 0 && gy < 64) {
                const float* rowp = X + (((size_t)b * C_ + c) * 64 + gy) * 64;
                int g0 = xc + 0 + kx, g1 = xc + 1 + kx, g2 = xc + 2 + kx, g3 = xc + 3 + kx;
                if (g0 >= 0 && g0 < 64) v0 = rowp[g0];
                if (g1 >= 0 && g1 < 64) v1 = rowp[g1];
                if (g2 >= 0 && g2 < 64) v2 = rowp[g2];
                if (g3 >= 0 && g3 < 64) v3 = rowp[g3];
            }
            *reinterpret_cast<float4*>(&Xs[kk][xc]) = make_float4(v0, v1, v2, v3);
        }
        {   // load W tile (oc-major in gmem, contiguous k) -> k-major smem
            int row = tid >> 2;            // oc
            int col = (tid & 3) * 4;       // k
            float4 wv = *reinterpret_cast<const float4*>(
                W + (size_t)row * KC_ + kc + col);
            Wt[col + 0][row] = wv.x;
            Wt[col + 1][row] = wv.y;
            Wt[col + 2][row] = wv.z;
            Wt[col + 3][row] = wv.w;
        }
        __syncthreads();
#pragma unroll
        for (int ks = 0; ks < 2; ks++) {
            int k0 = ks * 8;
            float af0 = Wt[k0 + lt    ][wm * 16 + lg];
            float af1 = Wt[k0 + lt    ][wm * 16 + lg + 8];
            float af2 = Wt[k0 + lt + 4][wm * 16 + lg];
            float af3 = Wt[k0 + lt + 4][wm * 16 + lg + 8];
            unsigned ah0 = f2tf(af0), ah1 = f2tf(af1), ah2 = f2tf(af2), ah3 = f2tf(af3);
            unsigned al0 = f2tf(af0 - __uint_as_float(ah0));
            unsigned al1 = f2tf(af1 - __uint_as_float(ah1));
            unsigned al2 = f2tf(af2 - __uint_as_float(ah2));
            unsigned al3 = f2tf(af3 - __uint_as_float(ah3));
#pragma unroll
            for (int j = 0; j < 4; j++) {
                int x0 = wn * 32 + j * 8;
                float bf0 = Xs[k0 + lt    ][x0 + lg];
                float bf1 = Xs[k0 + lt + 4][x0 + lg];
                unsigned bh0 = f2tf(bf0), bh1 = f2tf(bf1);
                unsigned bl0 = f2tf(bf0 - __uint_as_float(bh0));
                unsigned bl1 = f2tf(bf1 - __uint_as_float(bh1));
                MMA_TF32(d[j][0], d[j][1], d[j][2], d[j][3], ah0, ah1, ah2, ah3, bh0, bh1);
                MMA_TF32(d[j][0], d[j][1], d[j][2], d[j][3], ah0, ah1, ah2, ah3, bl0, bl1);
                MMA_TF32(d[j][0], d[j][1], d[j][2], d[j][3], al0, al1, al2, al3, bh0, bh1);
            }
        }
        __syncthreads();
    }

    int ocA = wm * 16 + lg;
    int ocB = ocA + 8;
    float biasA = bias[ocA];
    float biasB = bias[ocB];
    bool comp_y = (ocA & 1) != 0;
    float ybase = (2.f * (float)y - 63.f) * (1.f / 63.f);
    float* offb = &g_off[0] + (b * SQ_ + y * 64) * OC_;
#pragma unroll
    for (int j = 0; j < 4; j++) {
        int xp0 = wn * 32 + j * 8 + lt * 2;
        int xp1 = xp0 + 1;
        float base0 = comp_y ? ybase : (2.f * (float)xp0 - 63.f) * (1.f / 63.f);
        float base1 = comp_y ? ybase : (2.f * (float)xp1 - 63.f) * (1.f / 63.f);
        float f00 = (base0 + tanhf(d[j][0] + biasA) * 0.25f + 1.f) * 16.f - 0.5f;
        float f01 = (base1 + tanhf(d[j][1] + biasA) * 0.25f + 1.f) * 16.f - 0.5f;
        float f10 = (base0 + tanhf(d[j][2] + biasB) * 0.25f + 1.f) * 16.f - 0.5f;
        float f11 = (base1 + tanhf(d[j][3] + biasB) * 0.25f + 1.f) * 16.f - 0.5f;
        offb[xp0 * OC_ + ocA] = f00;
        offb[xp1 * OC_ + ocA] = f01;
        offb[xp0 * OC_ + ocB] = f10;
        offb[xp1 * OC_ + ocB] = f11;
    }
}

// ---------------------------------------------------------------------------
// Deformable attention: one warp per (n = b*8+head, pixel). lane = channel d.
// g_off holds final sample coords in kv pixel space. 32-bit pre-shifted
// element offsets (idx << 8 == idx * C_) to avoid 64-bit index math.
// ---------------------------------------------------------------------------
__global__ __launch_bounds__(256)
void attn_kernel() {
    int warp = threadIdx.x >> 5;
    int lane = threadIdx.x & 31;
    int n = blockIdx.y;                 // 0..63
    int s = blockIdx.x * 8 + warp;      // 0..4095
    int b = n >> 3, head = n & 7;

    int qoff = (b * SQ_ + s) * C_ + head * D_ + lane;
    float qd = g_q[qoff];
    const float* offp = &g_off[(b * SQ_ + s) * OC_ + head * (NP_ * 2)];
    const float* kb = &g_k[b * (SK_ * C_) + head * D_ + lane];
    const float* vb = &g_v[b * (SK_ * C_) + head * D_ + lane];

    float logit[NP_];
    int   tidx[NP_][4];
    float twgt[NP_][4];

#pragma unroll
    for (int p = 0; p < NP_; p++) {
        float fx = offp[2 * p + 0];
        float fy = offp[2 * p + 1];
        float x0 = floorf(fx), y0 = floorf(fy);
        float wx1 = fx - x0, wy1 = fy - y0;
        int x0i = (int)x0, y0i = (int)y0;

        float ks = 0.f;
#pragma unroll
        for (int t = 0; t < 4; t++) {
            int dy = t >> 1, dx = t & 1;
            int xi = x0i + dx, yi = y0i + dy;
            bool valid = (xi >= 0) && (xi < 32) && (yi >= 0) && (yi < 32);
            float wgt = (dx ? wx1 : 1.f - wx1) * (dy ? wy1 : 1.f - wy1);
            int eoff = ((yi << 5) + xi) << 8;   // element offset = idx * C_
            tidx[p][t] = valid ? eoff : -1;
            twgt[p][t] = valid ? wgt : 0.f;
            if (valid) ks += wgt * kb[eoff];
        }
        float dot = qd * ks;
#pragma unroll
        for (int o = 16; o > 0; o >>= 1)
            dot += __shfl_xor_sync(0xffffffffu, dot, o);
        logit[p] = dot * 0.17677669529663687f;  // 1/sqrt(32)
    }

    float m = fmaxf(fmaxf(logit[0], logit[1]), fmaxf(logit[2], logit[3]));
    float e0 = __expf(logit[0] - m);
    float e1 = __expf(logit[1] - m);
    float e2 = __expf(logit[2] - m);
    float e3 = __expf(logit[3] - m);
    float inv = 1.f / (e0 + e1 + e2 + e3);
    float a[NP_] = {e0 * inv, e1 * inv, e2 * inv, e3 * inv};

    float od = 0.f;
#pragma unroll
    for (int p = 0; p < NP_; p++)
#pragma unroll
        for (int t = 0; t < 4; t++)
            if (tidx[p][t] >= 0)
                od += a[p] * twgt[p][t] * vb[tidx[p][t]];

    g_att[qoff] = od;
}

// ---------------------------------------------------------------------------
// Launch
// ---------------------------------------------------------------------------
extern "C" void kernel_launch(void* const* d_in, const int* in_sizes, int n_in,
                              void* d_out, int out_size) {
    const float* query = (const float*)d_in[0];
    const float* kv    = (const float*)d_in[1];
    const float* q_w   = (const float*)d_in[2];
    const float* k_w   = (const float*)d_in[3];
    const float* v_w   = (const float*)d_in[4];
    const float* off_w = (const float*)d_in[5];
    const float* off_b = (const float*)d_in[6];
    const float* out_w = (const float*)d_in[7];
    float* out = (float*)d_out;

    dim3 blk16(16, 16);

    // projections (channel-last outputs)
    gemm_q_kernel <<<dim3(SQ_ / 64, C_ / 64, B_), blk16>>>(query, q_w);
    gemm_kv_kernel<<<dim3(SK_ / 64, C_ / 64, B_), blk16>>>(kv, k_w, v_w);

    // offset conv 3x3 as implicit GEMM on tensor cores + coord epilogue
    conv_off_mma_kernel<<<dim3(64, B_), 256>>>(query, off_w, off_b);

    // deformable attention
    attn_kernel<<<dim3(SQ_ / 8, B_ * NH_), 256>>>();

    // final projection to (B, C, H, W)
    gemm_out_kernel<<<dim3(SQ_ / 64, C_ / 64, B_), blk16>>>(out_w, out);
}